// round 3
// baseline (speedup 1.0000x reference)
#include <cuda_runtime.h>
#include <cstddef>

#define NB 16
#define NPT 4096
#define NS 1024
#define NK 32
#define MROWS (NB*NS*NK)

__device__ __align__(16) float g_pprime[(size_t)NB*NPT*64];
__device__ int                 g_gidx[MROWS];
__device__ __align__(16) float g_zA[(size_t)MROWS*128];
__device__ __align__(16) float g_zB[(size_t)MROWS*64];
__device__ double              g_stat[512];
__device__ float               g_scale[320];
__device__ float               g_shift[320];

__device__ __forceinline__ unsigned long long pk(float lo, float hi) {
    unsigned long long r;
    asm("mov.b64 %0, {%1,%2};" : "=l"(r) : "f"(lo), "f"(hi));
    return r;
}
__device__ __forceinline__ unsigned long long ffma2(unsigned long long a, unsigned long long b, unsigned long long c) {
    unsigned long long d;
    asm("fma.rn.f32x2 %0, %1, %2, %3;" : "=l"(d) : "l"(a), "l"(b), "l"(c));
    return d;
}
__device__ __forceinline__ void upk(unsigned long long v, float& lo, float& hi) {
    asm("mov.b64 {%0,%1}, %2;" : "=f"(lo), "=f"(hi) : "l"(v));
}

__global__ void zero_kernel() { if (threadIdx.x < 512) g_stat[threadIdx.x] = 0.0; }

// ---- FPS: 1 block/batch, 1024 threads, xyz in SMEM, writes new_xyz to d_out ----
__global__ void fps_kernel(const float* __restrict__ xyz, float* __restrict__ out_newxyz) {
    extern __shared__ float fsm[];
    float* sx = fsm; float* sy = fsm + NPT; float* sz = fsm + 2*NPT;
    unsigned long long* sred = (unsigned long long*)(fsm + 3*NPT);
    int* sfar = (int*)(sred + 32);
    int b = blockIdx.x, t = threadIdx.x;
    const float* p = xyz + (size_t)b*NPT*3;
    for (int i = t; i < NPT; i += 1024) { sx[i]=p[3*i]; sy[i]=p[3*i+1]; sz[i]=p[3*i+2]; }
    float dist[4];
    const float INF = __int_as_float(0x7f800000);
    #pragma unroll
    for (int j = 0; j < 4; j++) dist[j] = INF;
    int far = 0;
    __syncthreads();
    for (int it = 0; it < NS; it++) {
        if (t == 0) {
            size_t o = ((size_t)b*NS + it)*3;
            out_newxyz[o] = sx[far]; out_newxyz[o+1] = sy[far]; out_newxyz[o+2] = sz[far];
        }
        if (it == NS-1) break;
        float cx = sx[far], cy = sy[far], cz = sz[far];
        unsigned long long best = 0ull;
        #pragma unroll
        for (int j = 0; j < 4; j++) {
            int pi = t + j*1024;
            float tx = __fadd_rn(sx[pi], -cx), ty = __fadd_rn(sy[pi], -cy), tz = __fadd_rn(sz[pi], -cz);
            float d = __fadd_rn(__fadd_rn(__fmul_rn(tx,tx), __fmul_rn(ty,ty)), __fmul_rn(tz,tz));
            float nd = fminf(dist[j], d);
            dist[j] = nd;
            unsigned long long key = ((unsigned long long)__float_as_uint(nd) << 32)
                                   | (unsigned)(0xFFFFFFFFu - (unsigned)pi);
            best = best > key ? best : key;
        }
        #pragma unroll
        for (int o = 16; o > 0; o >>= 1) {
            unsigned long long v = __shfl_down_sync(0xffffffffu, best, o);
            best = best > v ? best : v;
        }
        if ((t & 31) == 0) sred[t >> 5] = best;
        __syncthreads();
        if (t < 32) {
            unsigned long long v = sred[t];
            #pragma unroll
            for (int o = 16; o > 0; o >>= 1) {
                unsigned long long w = __shfl_down_sync(0xffffffffu, v, o);
                v = v > w ? v : w;
            }
            if (t == 0) *sfar = (int)(0xFFFFFFFFu - (unsigned)(v & 0xFFFFFFFFull));
        }
        __syncthreads();
        far = *sfar;
    }
}

// ---- P' = W0_pts . points  -> (B,N,64) ----
__global__ void __launch_bounds__(256) pprime_kernel(const float* __restrict__ points, const float* __restrict__ w0) {
    __shared__ float Pts[64][128];
    __shared__ float Wt[64][64];
    int b = blockIdx.y, n0 = blockIdx.x*128, t = threadIdx.x;
    for (int i = t; i < 64*64; i += 256) { int o = i>>6, c = i&63; Wt[c][o] = w0[o*67 + 3 + c]; }
    const float* pb = points + (size_t)b*64*NPT;
    for (int i = t; i < 64*128/4; i += 256) {
        int e = i*4, c = e>>7, n = e&127;
        *(float4*)&Pts[c][n] = *(const float4*)(pb + (size_t)c*NPT + n0 + n);
    }
    __syncthreads();
    int cg = t & 15, rg = t >> 4;
    unsigned long long acc[8][2];
    #pragma unroll
    for (int i = 0; i < 8; i++) { acc[i][0]=0ull; acc[i][1]=0ull; }
    #pragma unroll 4
    for (int c = 0; c < 64; c++) {
        ulonglong2 wv = *(const ulonglong2*)&Wt[c][cg*4];
        #pragma unroll
        for (int i = 0; i < 8; i++) {
            float a = Pts[c][rg*8+i];
            unsigned long long aa = pk(a, a);
            acc[i][0] = ffma2(aa, wv.x, acc[i][0]);
            acc[i][1] = ffma2(aa, wv.y, acc[i][1]);
        }
    }
    float* outp = g_pprime + ((size_t)b*NPT + n0)*64;
    #pragma unroll
    for (int i = 0; i < 8; i++) {
        float4 v; upk(acc[i][0], v.x, v.y); upk(acc[i][1], v.z, v.w);
        *(float4*)(outp + (size_t)(rg*8+i)*64 + cg*4) = v;
    }
}

// ---- ball query: warp per query group, ordered ballot scan ----
__global__ void __launch_bounds__(256) bq_kernel(const float* __restrict__ xyz, const float* __restrict__ newxyz) {
    __shared__ float sx[NPT], sy[NPT], sz[NPT];
    int b = blockIdx.y, t = threadIdx.x, w = t>>5, lane = t&31;
    const float* p = xyz + (size_t)b*NPT*3;
    for (int i = t; i < NPT; i += 256) { sx[i]=p[3*i]; sy[i]=p[3*i+1]; sz[i]=p[3*i+2]; }
    __syncthreads();
    for (int q = 0; q < 4; q++) {
        int s = blockIdx.x*32 + w*4 + q;
        const float* nc = newxyz + ((size_t)b*NS + s)*3;
        float cx = nc[0], cy = nc[1], cz = nc[2];
        float cc = __fadd_rn(__fadd_rn(__fmul_rn(cx,cx), __fmul_rn(cy,cy)), __fmul_rn(cz,cz));
        int count = 0, first = 0;
        int* go = g_gidx + ((size_t)b*NS + s)*NK;
        for (int base = 0; base < NPT && count < NK; base += 32) {
            int pi = base + lane;
            float px = sx[pi], py = sy[pi], pz = sz[pi];
            float pp  = __fadd_rn(__fadd_rn(__fmul_rn(px,px), __fmul_rn(py,py)), __fmul_rn(pz,pz));
            float dot = __fadd_rn(__fadd_rn(__fmul_rn(cx,px), __fmul_rn(cy,py)), __fmul_rn(cz,pz));
            float sqr = __fadd_rn(__fadd_rn(cc, pp), -__fmul_rn(2.0f, dot));
            bool in = (sqr <= 0.04f);
            unsigned mask = __ballot_sync(0xffffffffu, in);
            if (count == 0 && mask) first = base + __ffs(mask) - 1;
            if (in) {
                int pos = count + __popc(mask & ((1u << lane) - 1u));
                if (pos < NK) go[pos] = pi;
            }
            count += __popc(mask);
        }
        if (count < NK && lane >= count) go[lane] = first;
    }
}

// ---- layer0: z0 = P'[gidx] + W0_xyz * (xyz[gidx]-center) ----
__global__ void l0_kernel(const float* __restrict__ xyz, const float* __restrict__ w0,
                          const float* __restrict__ newxyz) {
    __shared__ float wx[64], wy[64], wz[64];
    int t = threadIdx.x;
    if (t < 64) { wx[t]=w0[t*67]; wy[t]=w0[t*67+1]; wz[t]=w0[t*67+2]; }
    __syncthreads();
    size_t row = (size_t)blockIdx.x*256 + t;
    int s = (int)((row >> 5) & 1023), b = (int)(row >> 15);
    int g = g_gidx[row];
    const float* nc = newxyz + ((size_t)b*NS + s)*3;
    const float* pt = xyz + ((size_t)b*NPT + g)*3;
    float gx = pt[0]-nc[0], gy = pt[1]-nc[1], gz = pt[2]-nc[2];
    const float4* pr = (const float4*)(g_pprime + ((size_t)b*NPT + g)*64);
    float4* out = (float4*)(g_zA + row*64);
    #pragma unroll
    for (int qq = 0; qq < 16; qq++) {
        float4 v = pr[qq]; int o = qq*4;
        v.x = fmaf(wx[o  ], gx, fmaf(wy[o  ], gy, fmaf(wz[o  ], gz, v.x)));
        v.y = fmaf(wx[o+1], gx, fmaf(wy[o+1], gy, fmaf(wz[o+1], gz, v.y)));
        v.z = fmaf(wx[o+2], gx, fmaf(wy[o+2], gy, fmaf(wz[o+2], gz, v.z)));
        v.w = fmaf(wx[o+3], gx, fmaf(wy[o+3], gy, fmaf(wz[o+3], gz, v.w)));
        out[qq] = v;
    }
}

// ---- per-channel sum/sumsq ----
template<int C, int WHICH>
__global__ void stats_kernel(int statOff) {
    const float* Z = WHICH ? g_zB : g_zA;
    __shared__ double ssum[256], ssq[256];
    int t = threadIdx.x;
    constexpr int ITER = 2048 / (256 / C);
    size_t p = (size_t)blockIdx.x * (2048*C) + t;
    double s = 0.0, q = 0.0;
    for (int i = 0; i < ITER; i++) { double v = (double)Z[p]; s += v; q += v*v; p += 256; }
    ssum[t] = s; ssq[t] = q;
    __syncthreads();
    for (int off = 128; off >= C; off >>= 1) {
        if (t < off) { ssum[t] += ssum[t+off]; ssq[t] += ssq[t+off]; }
        __syncthreads();
    }
    if (t < C) {
        atomicAdd(&g_stat[statOff + t], ssum[t]);
        atomicAdd(&g_stat[statOff + C + t], ssq[t]);
    }
}

__global__ void finalize_kernel(int C, int statOff, int bnOff,
                                const float* __restrict__ g, const float* __restrict__ bb) {
    int c = threadIdx.x;
    if (c >= C) return;
    double inv = 1.0 / (double)MROWS;
    double mean = g_stat[statOff + c] * inv;
    double var  = g_stat[statOff + C + c] * inv - mean*mean;
    double sc = (double)g[c] / sqrt(var + 1e-5);
    g_scale[bnOff + c] = (float)sc;
    g_shift[bnOff + c] = (float)((double)bb[c] - mean * sc);
}

// ---- GEMM(K=64) with fused BN+ReLU on input tile, f32x2 FFMA ----
template<int COUT>
__global__ void __launch_bounds__(256) gemm_bn_kernel(const float* __restrict__ W) {
    constexpr int RPT = (COUT == 64) ? 8 : 16;
    constexpr int CG  = COUT / 4;
    constexpr int WST = COUT + 4;
    const float* X = (COUT == 64) ? g_zA : g_zB;
    float*       Y = (COUT == 64) ? g_zB : g_zA;
    const int bnOff = (COUT == 64) ? 0 : 64;
    extern __shared__ float sm[];
    float* Xs = sm;              // [128][68]
    float* Wt = sm + 128*68;     // [64][WST]
    int t = threadIdx.x;
    size_t row0 = (size_t)blockIdx.x * 128;
    {
        int c0 = (t*4) & 63;
        float s0=g_scale[bnOff+c0], s1=g_scale[bnOff+c0+1], s2=g_scale[bnOff+c0+2], s3=g_scale[bnOff+c0+3];
        float h0=g_shift[bnOff+c0], h1=g_shift[bnOff+c0+1], h2=g_shift[bnOff+c0+2], h3=g_shift[bnOff+c0+3];
        #pragma unroll
        for (int j = 0; j < 8; j++) {
            int e = t*4 + j*1024;
            float4 v = *(const float4*)(X + row0*64 + e);
            int r = e >> 6;
            float* xd = Xs + (size_t)r*68 + c0;
            xd[0] = fmaxf(fmaf(v.x, s0, h0), 0.f);
            xd[1] = fmaxf(fmaf(v.y, s1, h1), 0.f);
            xd[2] = fmaxf(fmaf(v.z, s2, h2), 0.f);
            xd[3] = fmaxf(fmaf(v.w, s3, h3), 0.f);
        }
    }
    for (int i = t; i < COUT*64; i += 256) {
        int o = i >> 6, c = i & 63;
        Wt[c*WST + o] = W[i];
    }
    __syncthreads();
    int cg = t % CG, rg = t / CG;
    unsigned long long acc[RPT][2];
    #pragma unroll
    for (int i = 0; i < RPT; i++) { acc[i][0]=0ull; acc[i][1]=0ull; }
    const float* xb = Xs + (size_t)(rg*RPT)*68;
    #pragma unroll 4
    for (int k = 0; k < 64; k++) {
        ulonglong2 wv = *(const ulonglong2*)(Wt + k*WST + cg*4);
        #pragma unroll
        for (int i = 0; i < RPT; i++) {
            float a = xb[i*68 + k];
            unsigned long long aa = pk(a, a);
            acc[i][0] = ffma2(aa, wv.x, acc[i][0]);
            acc[i][1] = ffma2(aa, wv.y, acc[i][1]);
        }
    }
    #pragma unroll
    for (int i = 0; i < RPT; i++) {
        float4 v; upk(acc[i][0], v.x, v.y); upk(acc[i][1], v.z, v.w);
        *(float4*)(Y + (row0 + rg*RPT + i)*COUT + cg*4) = v;
    }
}

// ---- BN2+ReLU+max over 32 samples, transposed store ----
__global__ void maxpool_kernel(float* __restrict__ out) {
    int o = threadIdx.x;
    size_t bs = blockIdx.x;
    const float* z = g_zA + bs*NK*128;
    float sc = g_scale[128 + o], sh = g_shift[128 + o];
    float m = 0.f;
    #pragma unroll
    for (int k = 0; k < NK; k++)
        m = fmaxf(m, fmaf(z[(size_t)k*128 + o], sc, sh));
    int b = (int)(bs >> 10), s = (int)(bs & 1023);
    out[(size_t)NB*NS*3 + ((size_t)b*128 + o)*NS + s] = m;
}

extern "C" void kernel_launch(void* const* d_in, const int* in_sizes, int n_in,
                              void* d_out, int out_size) {
    const float* xyz    = (const float*)d_in[0];
    const float* points = (const float*)d_in[1];
    const float* w0 = (const float*)d_in[2];
    const float* g0 = (const float*)d_in[3];
    const float* b0 = (const float*)d_in[4];
    const float* w1 = (const float*)d_in[5];
    const float* g1 = (const float*)d_in[6];
    const float* b1 = (const float*)d_in[7];
    const float* w2 = (const float*)d_in[8];
    const float* g2 = (const float*)d_in[9];
    const float* b2 = (const float*)d_in[10];
    float* out = (float*)d_out;

    const int FPS_SMEM = 3*NPT*4 + 32*8 + 16;
    cudaFuncSetAttribute(fps_kernel, cudaFuncAttributeMaxDynamicSharedMemorySize, FPS_SMEM);
    cudaFuncSetAttribute(gemm_bn_kernel<64>,  cudaFuncAttributeMaxDynamicSharedMemorySize, 128*68*4 + 64*68*4);
    cudaFuncSetAttribute(gemm_bn_kernel<128>, cudaFuncAttributeMaxDynamicSharedMemorySize, 128*68*4 + 64*132*4);

    zero_kernel<<<1, 512>>>();
    fps_kernel<<<NB, 1024, FPS_SMEM>>>(xyz, out);
    pprime_kernel<<<dim3(NPT/128, NB), 256>>>(points, w0);
    bq_kernel<<<dim3(NS/32, NB), 256>>>(xyz, out);
    l0_kernel<<<MROWS/256, 256>>>(xyz, w0, out);
    stats_kernel<64,0><<<256, 256>>>(0);
    finalize_kernel<<<1, 128>>>(64, 0, 0, g0, b0);
    gemm_bn_kernel<64><<<MROWS/128, 256, 128*68*4 + 64*68*4>>>(w1);
    stats_kernel<64,1><<<256, 256>>>(128);
    finalize_kernel<<<1, 128>>>(64, 128, 64, g1, b1);
    gemm_bn_kernel<128><<<MROWS/128, 256, 128*68*4 + 64*132*4>>>(w2);
    stats_kernel<128,0><<<256, 256>>>(256);
    finalize_kernel<<<1, 128>>>(128, 256, 128, g2, b2);
    maxpool_kernel<<<NB*NS, 128>>>(out);
    (void)in_sizes; (void)n_in; (void)out_size;
}